// round 15
// baseline (speedup 1.0000x reference)
#include <cuda_runtime.h>
#include <cuda_fp16.h>
#include <cstdint>

#define DD 1024
#define HH 1024
#define NB 8
#define NS 40
#define NL 20
#define MI 320        // B*N rows of f
#define MJ 160        // B*L rows of v
#define MG 51200      // MI*MJ grounding pairs
#define NPAIR 780     // triu_indices(40, k=1)
#define MT 6240       // B*NPAIR text rows
#define K3 3072

#define BM 128
#define BN 128
#define BK 32         // K per stage (fp16: 16 half2 units)
#define ASTR 520      // plane stride in u32: BM*4 + 8 (conflict-free chunks)

// Scratch (static device globals; no runtime allocation anywhere)
__device__ float    g_Apre[MI * HH];               // f @ Wf (fp32)
__device__ float    g_Cpre[MJ * HH];               // v @ Ws (fp32)
// H1/Xt/Ht stored as packed half2 in TILE-PLANE order per row:
//   u32 idx = (kk/16)*16 + (kk&3)*4 + ((kk>>2)&3), kk = k/2
__device__ uint32_t g_H1[(size_t)MG * HH / 2];
__device__ uint32_t g_Xt[(size_t)MT * K3 / 2];
__device__ uint32_t g_Ht[(size_t)MT * HH / 2];
// Pre-transformed fp16 weights, tile-plane layout on kk = k/2:
//   WT[((kk/16)*4 + (kk&3)) * (HH*4) + n*4 + ((kk>>2)&3)] = half2(W[2kk][n], W[2kk+1][n])
__device__ uint32_t g_WpT[DD * HH / 2];
__device__ uint32_t g_W1T[(size_t)K3 * HH / 2];
__device__ uint32_t g_W2gT[HH * HH / 2];
__device__ uint32_t g_W2tT[HH * HH / 2];

// ---------------------------------------------------------------------------
// Helpers
// ---------------------------------------------------------------------------
__device__ __forceinline__ uint32_t pack_h2(float lo, float hi) {
    __half2 h = __floats2half2_rn(lo, hi);
    return *(uint32_t*)&h;
}

// Row-local permuted index for tile-plane layout (kk = half2 index in row)
__device__ __forceinline__ int tp_idx(int kk) {
    return ((kk >> 4) << 4) + ((kk & 3) << 2) + ((kk >> 2) & 3);
}

__device__ __forceinline__ void mma_f16(float* c,
    uint32_t a0, uint32_t a1, uint32_t a2, uint32_t a3,
    uint32_t b0, uint32_t b1)
{
    asm volatile(
        "mma.sync.aligned.m16n8k16.row.col.f32.f16.f16.f32 "
        "{%0,%1,%2,%3}, {%4,%5,%6,%7}, {%8,%9}, {%0,%1,%2,%3};\n"
        : "+f"(c[0]), "+f"(c[1]), "+f"(c[2]), "+f"(c[3])
        : "r"(a0), "r"(a1), "r"(a2), "r"(a3), "r"(b0), "r"(b1));
}

__device__ __forceinline__ void cp16ca(uint32_t saddr, const void* g) {
    asm volatile("cp.async.ca.shared.global [%0], [%1], 16;\n"
                 :: "r"(saddr), "l"(g) : "memory");
}
__device__ __forceinline__ void cp16cgz(uint32_t saddr, const void* g, int srcsz) {
    asm volatile("cp.async.cg.shared.global [%0], [%1], 16, %2;\n"
                 :: "r"(saddr), "l"(g), "r"(srcsz) : "memory");
}
#define CP_COMMIT() asm volatile("cp.async.commit_group;\n" ::: "memory")
#define CP_WAIT0()  asm volatile("cp.async.wait_group 0;\n" ::: "memory")

// Weight transform: W[K x 1024] fp32 -> packed-half2 tile-plane layout.
__global__ void wconv_kernel(const float* __restrict__ W, int dst_sel, int K)
{
    uint32_t* out = (dst_sel == 0) ? g_WpT : (dst_sel == 1) ? g_W1T
                  : (dst_sel == 2) ? g_W2gT : g_W2tT;
    int id = blockIdx.x * 256 + threadIdx.x;
    if (id >= K * 512) return;
    int t = id & 3, n = (id >> 2) & 1023;
    int q = (id >> 12) & 3, tile = id >> 14;
    int k0 = 2 * (tile * 16 + q + 4 * t);
    out[id] = pack_h2(W[(size_t)k0 * 1024 + n], W[(size_t)(k0 + 1) * 1024 + n]);
}

// Smem layout (on kk): element (kk, x) at plane (kk&3), offset x*4 + (kk>>2).
__device__ __forceinline__ void mma_stage_f16(
    const uint32_t* __restrict__ Asb, const uint32_t* __restrict__ Bsb,
    int wrow, int wcol, int fr, int fc, float acc[4][4][4])
{
    const uint32_t* ab = Asb + fc * ASTR;
    const uint32_t* bb = Bsb + fc * ASTR;
    uint4 alo[4], ahi[4];
    #pragma unroll
    for (int mt = 0; mt < 4; mt++) {
        int m = wrow + mt * 16 + fr;
        alo[mt] = *(const uint4*)&ab[m * 4];
        ahi[mt] = *(const uint4*)&ab[(m + 8) * 4];
    }
    #pragma unroll
    for (int nt = 0; nt < 4; nt++) {
        int n = wcol + nt * 8 + fr;
        uint4 bq = *(const uint4*)&bb[n * 4];
        #pragma unroll
        for (int mt = 0; mt < 4; mt++) {
            mma_f16(acc[mt][nt], alo[mt].x, ahi[mt].x, alo[mt].y, ahi[mt].y, bq.x, bq.y);
            mma_f16(acc[mt][nt], alo[mt].z, ahi[mt].z, alo[mt].w, ahi[mt].w, bq.z, bq.w);
        }
    }
}

// ---------------------------------------------------------------------------
// Grounding layer 1 (fused A-gen). A: fp32 product + pack + STS (registers);
// B: cp.async from pre-transformed g_WpT.
// ---------------------------------------------------------------------------
__global__ __launch_bounds__(256, 2) void ground_h1_tc(
    const float* __restrict__ f, const float* __restrict__ v,
    const float* __restrict__ b1)
{
    __shared__ uint32_t As[2][4 * ASTR];
    __shared__ uint32_t Bs[2][4 * ASTR];
    int tid = threadIdx.x;
    int lane = tid & 31, wid = tid >> 5;
    int wm = wid & 1, wn = wid >> 1;
    int wrow = wm * 64, wcol = wn * 32;
    int fr = lane >> 2, fc = lane & 3;
    int row0 = blockIdx.y * BM, col0 = blockIdx.x * BN;

    uint32_t sB[2] = { (uint32_t)__cvta_generic_to_shared(&Bs[0][0]),
                       (uint32_t)__cvta_generic_to_shared(&Bs[1][0]) };

    int amM[2], amK[2];
    size_t aF[2], aV[2], bOff[2];
    uint32_t bDst[2];
    #pragma unroll
    for (int l = 0; l < 2; l++) {
        int idx = tid + l * 256;
        amM[l] = idx >> 2; amK[l] = idx & 3;
        int gr = row0 + amM[l];
        int gi = gr / MJ, gj = gr - gi * MJ;
        aF[l] = (size_t)gi * DD; aV[l] = (size_t)gj * DD;
        int bn = idx & 127, bc = idx >> 7;
        bOff[l] = (size_t)bc * (HH * 4) + (size_t)(col0 + bn) * 4;
        bDst[l] = (uint32_t)(bc * ASTR + bn * 4) * 4;
    }

    uint4 aU[2];
    #pragma unroll
    for (int l = 0; l < 2; l++) {
        size_t ka = amK[l] * 8;
        float4 fa = *(const float4*)&f[aF[l] + ka];
        float4 fb = *(const float4*)&f[aF[l] + ka + 4];
        float4 va = *(const float4*)&v[aV[l] + ka];
        float4 vb = *(const float4*)&v[aV[l] + ka + 4];
        aU[l] = make_uint4(pack_h2(fa.x * va.x, fa.y * va.y),
                           pack_h2(fa.z * va.z, fa.w * va.w),
                           pack_h2(fb.x * vb.x, fb.y * vb.y),
                           pack_h2(fb.z * vb.z, fb.w * vb.w));
        cp16ca(sB[0] + bDst[l], g_WpT + bOff[l]);
    }
    CP_COMMIT();

    float acc[4][4][4] = {};
    int p = 0;
    for (int kt = 0; kt < DD; kt += BK) {
        #pragma unroll
        for (int l = 0; l < 2; l++) {
            As[p][0 * ASTR + amM[l] * 4 + amK[l]] = aU[l].x;
            As[p][1 * ASTR + amM[l] * 4 + amK[l]] = aU[l].y;
            As[p][2 * ASTR + amM[l] * 4 + amK[l]] = aU[l].z;
            As[p][3 * ASTR + amM[l] * 4 + amK[l]] = aU[l].w;
        }
        CP_WAIT0();
        __syncthreads();
        int ktn = kt + BK;
        if (ktn < DD) {
            #pragma unroll
            for (int l = 0; l < 2; l++) {
                size_t ka = ktn + amK[l] * 8;
                float4 fa = *(const float4*)&f[aF[l] + ka];
                float4 fb = *(const float4*)&f[aF[l] + ka + 4];
                float4 va = *(const float4*)&v[aV[l] + ka];
                float4 vb = *(const float4*)&v[aV[l] + ka + 4];
                aU[l] = make_uint4(pack_h2(fa.x * va.x, fa.y * va.y),
                                   pack_h2(fa.z * va.z, fa.w * va.w),
                                   pack_h2(fb.x * vb.x, fb.y * vb.y),
                                   pack_h2(fb.z * vb.z, fb.w * vb.w));
                cp16ca(sB[p ^ 1] + bDst[l],
                       g_WpT + (size_t)(ktn >> 5) * (HH * 16) + bOff[l]);
            }
        }
        CP_COMMIT();
        mma_stage_f16(As[p], Bs[p], wrow, wcol, fr, fc, acc);
        p ^= 1;
    }

    #pragma unroll
    for (int mt = 0; mt < 4; mt++) {
        #pragma unroll
        for (int h = 0; h < 2; h++) {
            int r = row0 + wrow + mt * 16 + fr + h * 8;
            int gi = r / MJ, gj = r - gi * MJ;
            const float* ap = &g_Apre[(size_t)gi * HH];
            const float* cp = &g_Cpre[(size_t)gj * HH];
            uint32_t* hp = &g_H1[(size_t)r * (HH / 2)];
            #pragma unroll
            for (int nt = 0; nt < 4; nt++) {
                int c = col0 + wcol + nt * 8 + fc * 2;
                float x0 = acc[mt][nt][h * 2 + 0] + ap[c] + cp[c] + b1[c];
                float x1 = acc[mt][nt][h * 2 + 1] + ap[c + 1] + cp[c + 1] + b1[c + 1];
                hp[tp_idx(c >> 1)] = pack_h2(fmaxf(x0, 0.f), fmaxf(x1, 0.f));
            }
        }
    }
}

// ---------------------------------------------------------------------------
// Text layer 1: g_Ht = relu(g_Xt @ tW1 + tb1). A and B both via cp.async.
// ---------------------------------------------------------------------------
__global__ __launch_bounds__(256, 2) void text1_tc(const float* __restrict__ b1)
{
    __shared__ uint32_t As[2][4 * ASTR];
    __shared__ uint32_t Bs[2][4 * ASTR];
    int tid = threadIdx.x;
    int lane = tid & 31, wid = tid >> 5;
    int wm = wid & 1, wn = wid >> 1;
    int wrow = wm * 64, wcol = wn * 32;
    int fr = lane >> 2, fc = lane & 3;
    int row0 = blockIdx.y * BM, col0 = blockIdx.x * BN;

    uint32_t sA[2] = { (uint32_t)__cvta_generic_to_shared(&As[0][0]),
                       (uint32_t)__cvta_generic_to_shared(&As[1][0]) };
    uint32_t sB[2] = { (uint32_t)__cvta_generic_to_shared(&Bs[0][0]),
                       (uint32_t)__cvta_generic_to_shared(&Bs[1][0]) };

    int aSz[2];
    size_t aSrc[2], bOff[2];
    uint32_t aDst[2], bDst[2];
    #pragma unroll
    for (int l = 0; l < 2; l++) {
        int idx = tid + l * 256;
        int m = idx >> 2, q = idx & 3;
        int gr = row0 + m;
        aSz[l] = (gr < MT) ? 16 : 0;
        aSrc[l] = (size_t)((gr < MT) ? gr : 0) * (K3 / 2) + q * 4;
        aDst[l] = (uint32_t)(q * ASTR + m * 4) * 4;
        int bn = idx & 127, bc = idx >> 7;
        bOff[l] = (size_t)bc * (HH * 4) + (size_t)(col0 + bn) * 4;
        bDst[l] = (uint32_t)(bc * ASTR + bn * 4) * 4;
    }

    #pragma unroll
    for (int l = 0; l < 2; l++) {
        cp16cgz(sA[0] + aDst[l], g_Xt + aSrc[l], aSz[l]);
        cp16ca(sB[0] + bDst[l], g_W1T + bOff[l]);
    }
    CP_COMMIT();

    float acc[4][4][4] = {};
    int p = 0;
    for (int kt = 0; kt < K3; kt += BK) {
        CP_WAIT0();
        __syncthreads();
        int ktn = kt + BK;
        if (ktn < K3) {
            #pragma unroll
            for (int l = 0; l < 2; l++) {
                cp16cgz(sA[p ^ 1] + aDst[l], g_Xt + aSrc[l] + (ktn >> 5) * 16, aSz[l]);
                cp16ca(sB[p ^ 1] + bDst[l],
                       g_W1T + (size_t)(ktn >> 5) * (HH * 16) + bOff[l]);
            }
        }
        CP_COMMIT();
        mma_stage_f16(As[p], Bs[p], wrow, wcol, fr, fc, acc);
        p ^= 1;
    }

    #pragma unroll
    for (int mt = 0; mt < 4; mt++) {
        #pragma unroll
        for (int h = 0; h < 2; h++) {
            int r = row0 + wrow + mt * 16 + fr + h * 8;
            if (r >= MT) continue;
            uint32_t* hp = &g_Ht[(size_t)r * (HH / 2)];
            #pragma unroll
            for (int nt = 0; nt < 4; nt++) {
                int c = col0 + wcol + nt * 8 + fc * 2;
                float x0 = acc[mt][nt][h * 2 + 0] + b1[c];
                float x1 = acc[mt][nt][h * 2 + 1] + b1[c + 1];
                hp[tp_idx(c >> 1)] = pack_h2(fmaxf(x0, 0.f), fmaxf(x1, 0.f));
            }
        }
    }
}

// ---------------------------------------------------------------------------
// Fused tail: out[r] = relu(H[r,:]@W2 + b2) @ W3 + b3 (optional mask).
// A and B via cp.async. h_sel: 0 -> g_H1/g_W2gT, 1 -> g_Ht/g_W2tT.
// ---------------------------------------------------------------------------
__global__ __launch_bounds__(256, 2) void tail_tc(
    int h_sel, const float* __restrict__ b2, const float* __restrict__ W3,
    const float* __restrict__ b3v, const float* __restrict__ sm,
    const float* __restrict__ im, float* __restrict__ outp,
    int M, int masked)
{
    const uint32_t* Hm = (h_sel == 0) ? g_H1 : g_Ht;
    const uint32_t* W2T = (h_sel == 0) ? g_W2gT : g_W2tT;
    __shared__ uint32_t As[2][4 * ASTR];
    __shared__ uint32_t Bs[2][4 * ASTR];
    __shared__ float red[BM * 16];
    int tid = threadIdx.x;
    int lane = tid & 31, wid = tid >> 5;
    int wm = wid & 1, wn = wid >> 1;
    int wrow = wm * 64, wcol = wn * 32;
    int fr = lane >> 2, fc = lane & 3;
    int row0 = blockIdx.x * BM;
    float rsum[4][2] = {};

    uint32_t sA[2] = { (uint32_t)__cvta_generic_to_shared(&As[0][0]),
                       (uint32_t)__cvta_generic_to_shared(&As[1][0]) };
    uint32_t sB[2] = { (uint32_t)__cvta_generic_to_shared(&Bs[0][0]),
                       (uint32_t)__cvta_generic_to_shared(&Bs[1][0]) };

    int aSz[2], bnN[2], bcC[2];
    size_t aSrc[2], bCol[2];
    uint32_t aDst[2], bDst[2];
    #pragma unroll
    for (int l = 0; l < 2; l++) {
        int idx = tid + l * 256;
        int m = idx >> 2, q = idx & 3;
        int gr = row0 + m;
        aSz[l] = (gr < M) ? 16 : 0;
        aSrc[l] = (size_t)((gr < M) ? gr : 0) * (HH / 2) + q * 4;
        aDst[l] = (uint32_t)(q * ASTR + m * 4) * 4;
        bnN[l] = idx & 127; bcC[l] = idx >> 7;
        bCol[l] = (size_t)bcC[l] * (HH * 4);
        bDst[l] = (uint32_t)(bcC[l] * ASTR + bnN[l] * 4) * 4;
    }

    int p = 0;
    for (int nc = 0; nc < HH; nc += BN) {
        __syncthreads();   // buffer reuse guard across chunks
        #pragma unroll
        for (int l = 0; l < 2; l++) {
            cp16cgz(sA[p] + aDst[l], Hm + aSrc[l], aSz[l]);
            cp16ca(sB[p] + bDst[l], W2T + bCol[l] + (size_t)(nc + bnN[l]) * 4);
        }
        CP_COMMIT();

        float acc[4][4][4] = {};
        for (int kt = 0; kt < HH; kt += BK) {
            CP_WAIT0();
            __syncthreads();
            int ktn = kt + BK;
            if (ktn < HH) {
                #pragma unroll
                for (int l = 0; l < 2; l++) {
                    cp16cgz(sA[p ^ 1] + aDst[l], Hm + aSrc[l] + (ktn >> 5) * 16, aSz[l]);
                    cp16ca(sB[p ^ 1] + bDst[l],
                           W2T + (size_t)(ktn >> 5) * (HH * 16) + bCol[l]
                               + (size_t)(nc + bnN[l]) * 4);
                }
            }
            CP_COMMIT();
            mma_stage_f16(As[p], Bs[p], wrow, wcol, fr, fc, acc);
            p ^= 1;
        }
        #pragma unroll
        for (int mt = 0; mt < 4; mt++) {
            #pragma unroll
            for (int nt = 0; nt < 4; nt++) {
                int c = nc + wcol + nt * 8 + fc * 2;
                float w30 = W3[c], w31 = W3[c + 1];
                float b20 = b2[c], b21 = b2[c + 1];
                rsum[mt][0] += fmaxf(acc[mt][nt][0] + b20, 0.f) * w30
                             + fmaxf(acc[mt][nt][1] + b21, 0.f) * w31;
                rsum[mt][1] += fmaxf(acc[mt][nt][2] + b20, 0.f) * w30
                             + fmaxf(acc[mt][nt][3] + b21, 0.f) * w31;
            }
        }
    }

    #pragma unroll
    for (int mt = 0; mt < 4; mt++)
        #pragma unroll
        for (int h = 0; h < 2; h++) {
            int row = wrow + mt * 16 + fr + h * 8;
            red[row * 16 + wn * 4 + fc] = rsum[mt][h];
        }
    __syncthreads();
    if (tid < BM) {
        int r = row0 + tid;
        if (r < M) {
            float s = 0.f;
            #pragma unroll
            for (int t = 0; t < 16; t++) s += red[tid * 16 + t];
            s += b3v[0];
            if (masked) {
                int gi = r / MJ, gj = r - gi * MJ;
                s *= sm[gi] * im[gj];
            }
            outp[r] = s;
        }
    }
}

// ---------------------------------------------------------------------------
// Small SGEMM (fp32, 64x64 tile) for the two tiny pre-GEMMs f@Wf, v@Ws.
// ---------------------------------------------------------------------------
__global__ __launch_bounds__(256) void sgemm_small(
    const float* __restrict__ A, const float* __restrict__ Bm,
    int c_sel, int M, int N, int K)
{
    float* C = (c_sel == 0) ? g_Apre : g_Cpre;
    __shared__ __align__(16) float As[16][66];
    __shared__ __align__(16) float Bs[16][64];
    int tid = threadIdx.x;
    int tx = tid & 15, ty = tid >> 4;
    int row0 = blockIdx.y * 64, col0 = blockIdx.x * 64;
    float acc[4][4] = {};
    for (int kt = 0; kt < K; kt += 16) {
        #pragma unroll
        for (int l = 0; l < 4; l++) {
            int idx = tid + l * 256;
            int m = idx >> 4, kk = idx & 15;
            int gr = row0 + m;
            As[kk][m] = (gr < M) ? A[(size_t)gr * K + kt + kk] : 0.f;
        }
        #pragma unroll
        for (int l = 0; l < 4; l++) {
            int idx = tid + l * 256;
            int kk = idx >> 6, c = idx & 63;
            Bs[kk][c] = Bm[(size_t)(kt + kk) * N + col0 + c];
        }
        __syncthreads();
        #pragma unroll
        for (int kk = 0; kk < 16; kk++) {
            float av[4];
            #pragma unroll
            for (int i = 0; i < 4; i++) av[i] = As[kk][ty * 4 + i];
            float4 b4 = *(const float4*)&Bs[kk][tx * 4];
            float bv[4] = {b4.x, b4.y, b4.z, b4.w};
            #pragma unroll
            for (int i = 0; i < 4; i++)
                #pragma unroll
                for (int j = 0; j < 4; j++)
                    acc[i][j] += av[i] * bv[j];
        }
        __syncthreads();
    }
    #pragma unroll
    for (int i = 0; i < 4; i++) {
        int r = row0 + ty * 4 + i;
        if (r >= M) continue;
        #pragma unroll
        for (int j = 0; j < 4; j++)
            C[(size_t)r * N + col0 + tx * 4 + j] = acc[i][j];
    }
}

// ---------------------------------------------------------------------------
// Build text concat input (packed half2, tile-plane permuted per row):
// parts: [span[fi], span[si], span[fi]*span[si]]
// ---------------------------------------------------------------------------
__global__ void build_xt_kernel(const float* __restrict__ span)
{
    int r = blockIdx.x;
    int b = r / NPAIR, p = r - b * NPAIR;
    int n = 0, rem = p;
    while (rem >= (NS - 1 - n)) { rem -= (NS - 1 - n); n++; }
    int fi = n, si = n + 1 + rem;
    const float2* a2 = (const float2*)(span + ((size_t)b * NS + fi) * DD);
    const float2* c2 = (const float2*)(span + ((size_t)b * NS + si) * DD);
    uint32_t* x = g_Xt + (size_t)r * (K3 / 2);
    for (int kk = threadIdx.x; kk < K3 / 2; kk += blockDim.x) {
        int part = kk / (DD / 2);
        int dd = kk - part * (DD / 2);
        float2 aa = a2[dd], cc = c2[dd];
        float lo, hi;
        if (part == 0)      { lo = aa.x;        hi = aa.y; }
        else if (part == 1) { lo = cc.x;        hi = cc.y; }
        else                { lo = aa.x * cc.x; hi = aa.y * cc.y; }
        x[tp_idx(kk)] = pack_h2(lo, hi);
    }
}

// ---------------------------------------------------------------------------
// S[8][8] = chunk sums of 800 grounding scores; loss = bidirectional NCE.
// ---------------------------------------------------------------------------
__global__ void loss_kernel(const float* __restrict__ gsc, float* __restrict__ out0)
{
    __shared__ float S[64];
    __shared__ float red[256];
    int tid = threadIdx.x;
    int e = tid >> 2, q = tid & 3;
    float s = 0.f;
    const float* base = gsc + e * 800;
    for (int k = q; k < 800; k += 4) s += base[k];
    red[tid] = s;
    __syncthreads();
    if (q == 0) S[e] = red[tid] + red[tid + 1] + red[tid + 2] + red[tid + 3];
    __syncthreads();
    if (tid == 0) {
        float loss = 0.f;
        for (int a = 0; a < 8; a++) {
            float mx = -1e30f;
            for (int b = 0; b < 8; b++) mx = fmaxf(mx, S[a * 8 + b]);
            float se = 0.f;
            for (int b = 0; b < 8; b++) se += expf(S[a * 8 + b] - mx);
            float lse = mx + logf(se);
            for (int b = 0; b < 8; b++) loss -= (S[a * 8 + b] - lse);
        }
        for (int b = 0; b < 8; b++) {
            float mx = -1e30f;
            for (int a = 0; a < 8; a++) mx = fmaxf(mx, S[a * 8 + b]);
            float se = 0.f;
            for (int a = 0; a < 8; a++) se += expf(S[a * 8 + b] - mx);
            float lse = mx + logf(se);
            for (int a = 0; a < 8; a++) loss -= (S[a * 8 + b] - lse);
        }
        out0[0] = loss / 8.0f;
    }
}

extern "C" void kernel_launch(void* const* d_in, const int* in_sizes, int n_in,
                              void* d_out, int out_size)
{
    const float* span  = (const float*)d_in[0];
    const float* img   = (const float*)d_in[1];
    const float* smask = (const float*)d_in[2];
    const float* imask = (const float*)d_in[3];
    const float* tW1 = (const float*)d_in[4];
    const float* tb1 = (const float*)d_in[5];
    const float* tW2 = (const float*)d_in[6];
    const float* tb2 = (const float*)d_in[7];
    const float* tW3 = (const float*)d_in[8];
    const float* tb3 = (const float*)d_in[9];
    const float* gW1 = (const float*)d_in[10];
    const float* gb1 = (const float*)d_in[11];
    const float* gW2 = (const float*)d_in[12];
    const float* gb2 = (const float*)d_in[13];
    const float* gW3 = (const float*)d_in[14];
    const float* gb3 = (const float*)d_in[15];
    float* out = (float*)d_out;

    dim3 blk(256);

    // Fork a second stream for the independent text path (capture-legal
    // fork/join via events).
    cudaStream_t s2;
    cudaStreamCreateWithFlags(&s2, cudaStreamNonBlocking);
    cudaEvent_t evFork, evJoin;
    cudaEventCreateWithFlags(&evFork, cudaEventDisableTiming);
    cudaEventCreateWithFlags(&evJoin, cudaEventDisableTiming);

    cudaEventRecord(evFork, 0);
    cudaStreamWaitEvent(s2, evFork, 0);

    // ---- Text path on s2 ----
    wconv_kernel<<<(K3 * 512 + 255) / 256, blk, 0, s2>>>(tW1, 1, K3);
    wconv_kernel<<<(HH * 512 + 255) / 256, blk, 0, s2>>>(tW2, 3, HH);
    build_xt_kernel<<<dim3(MT), blk, 0, s2>>>(span);
    text1_tc<<<dim3(HH / BN, (MT + BM - 1) / BM), blk, 0, s2>>>(tb1);
    tail_tc<<<dim3((MT + BM - 1) / BM), blk, 0, s2>>>(1, tb2, tW3, tb3,
                                                      nullptr, nullptr,
                                                      out + 1 + MG, MT, 0);
    cudaEventRecord(evJoin, s2);

    // ---- Grounding path on the capture (default) stream ----
    wconv_kernel<<<(DD * 512 + 255) / 256, blk>>>(gW1 + (size_t)2 * DD * HH, 0, DD);
    wconv_kernel<<<(HH * 512 + 255) / 256, blk>>>(gW2, 2, HH);
    sgemm_small<<<dim3(16, 5), blk>>>(span, gW1, 0, MI, HH, DD);
    sgemm_small<<<dim3(16, 3), blk>>>(img, gW1 + (size_t)DD * HH, 1, MJ, HH, DD);
    ground_h1_tc<<<dim3(HH / BN, MG / BM), blk>>>(span, img, gb1);
    tail_tc<<<dim3(MG / BM), blk>>>(0, gb2, gW3, gb3, smask, imask, out + 1, MG, 1);

    // Join text path before the final reduction.
    cudaStreamWaitEvent(0, evJoin, 0);
    loss_kernel<<<1, 256>>>(out + 1, out);
}

// round 16
// speedup vs baseline: 1.1112x; 1.1112x over previous
#include <cuda_runtime.h>
#include <cuda_fp16.h>
#include <cstdint>

#define DD 1024
#define HH 1024
#define NB 8
#define NS 40
#define NL 20
#define MI 320        // B*N rows of f
#define MJ 160        // B*L rows of v
#define MG 51200      // MI*MJ grounding pairs
#define NPAIR 780     // triu_indices(40, k=1)
#define MT 6240       // B*NPAIR text rows
#define K3 3072

#define BM 128
#define BN 128
#define BK 32         // K per stage (fp16: 16 half2 units)
#define ASTR 520      // plane stride in u32: BM*4 + 8 (conflict-free chunks)

// Scratch (static device globals; no runtime allocation anywhere)
__device__ float    g_Apre[MI * HH];               // f @ Wf (fp32)
__device__ float    g_Cpre[MJ * HH];               // v @ Ws (fp32)
__device__ uint32_t g_H1[(size_t)MG * HH / 2];     // grounding hidden (half2)
__device__ uint32_t g_Xt[(size_t)MT * K3 / 2];     // text concat input (half2)
__device__ uint32_t g_Ht[(size_t)MT * HH / 2];     // text hidden (half2)
// Pre-transformed fp16 weights, tile-plane layout on kk = k/2:
//   WT[((kk/16)*4 + (kk&3)) * (HH*4) + n*4 + ((kk>>2)&3)] = half2(W[2kk][n], W[2kk+1][n])
__device__ uint32_t g_WpT[DD * HH / 2];
__device__ uint32_t g_W1T[(size_t)K3 * HH / 2];
__device__ uint32_t g_W2gT[HH * HH / 2];
__device__ uint32_t g_W2tT[HH * HH / 2];

// ---------------------------------------------------------------------------
// FP16 helpers
// ---------------------------------------------------------------------------
__device__ __forceinline__ uint32_t pack_h2(float lo, float hi) {
    __half2 h = __floats2half2_rn(lo, hi);
    return *(uint32_t*)&h;
}

__device__ __forceinline__ void mma_f16(float* c,
    uint32_t a0, uint32_t a1, uint32_t a2, uint32_t a3,
    uint32_t b0, uint32_t b1)
{
    asm volatile(
        "mma.sync.aligned.m16n8k16.row.col.f32.f16.f16.f32 "
        "{%0,%1,%2,%3}, {%4,%5,%6,%7}, {%8,%9}, {%0,%1,%2,%3};\n"
        : "+f"(c[0]), "+f"(c[1]), "+f"(c[2]), "+f"(c[3])
        : "r"(a0), "r"(a1), "r"(a2), "r"(a3), "r"(b0), "r"(b1));
}

// Weight transform: W[K x 1024] fp32 -> packed-half2 tile-plane layout.
__global__ void wconv_kernel(const float* __restrict__ W, int dst_sel, int K)
{
    uint32_t* out = (dst_sel == 0) ? g_WpT : (dst_sel == 1) ? g_W1T
                  : (dst_sel == 2) ? g_W2gT : g_W2tT;
    int id = blockIdx.x * 256 + threadIdx.x;
    if (id >= K * 512) return;
    int t = id & 3, n = (id >> 2) & 1023;
    int q = (id >> 12) & 3, tile = id >> 14;
    int k0 = 2 * (tile * 16 + q + 4 * t);
    out[id] = pack_h2(W[(size_t)k0 * 1024 + n], W[(size_t)(k0 + 1) * 1024 + n]);
}

// Smem layout (on kk = k/2): element (kk, x) at plane (kk&3), offset x*4 + (kk>>2).
// One uint4 at plane fc yields kk = fc, fc+4, fc+8, fc+12 — fragments of BOTH
// m16n8k16 MMAs (k 0-15 via .x/.y, k 16-31 via .z/.w).
__device__ __forceinline__ void mma_stage_f16(
    const uint32_t* __restrict__ Asb, const uint32_t* __restrict__ Bsb,
    int wrow, int wcol, int fr, int fc, float acc[4][4][4])
{
    const uint32_t* ab = Asb + fc * ASTR;
    const uint32_t* bb = Bsb + fc * ASTR;
    uint4 alo[4], ahi[4];
    #pragma unroll
    for (int mt = 0; mt < 4; mt++) {
        int m = wrow + mt * 16 + fr;
        alo[mt] = *(const uint4*)&ab[m * 4];
        ahi[mt] = *(const uint4*)&ab[(m + 8) * 4];
    }
    #pragma unroll
    for (int nt = 0; nt < 4; nt++) {
        int n = wcol + nt * 8 + fr;
        uint4 bq = *(const uint4*)&bb[n * 4];
        #pragma unroll
        for (int mt = 0; mt < 4; mt++) {
            mma_f16(acc[mt][nt], alo[mt].x, ahi[mt].x, alo[mt].y, ahi[mt].y, bq.x, bq.y);
            mma_f16(acc[mt][nt], alo[mt].z, ahi[mt].z, alo[mt].w, ahi[mt].w, bq.z, bq.w);
        }
    }
}

// Staging stores (register-staged A + B). A: 4 STS.32 planes; B: 1 STS.128.
__device__ __forceinline__ void sts_stage_u32(
    uint32_t* Asb, uint32_t* Bsb,
    const int* amM, const int* amK, const int* bnN, const int* bcC,
    const uint4* aU, const uint4* bU)
{
    #pragma unroll
    for (int l = 0; l < 2; l++) {
        Asb[0 * ASTR + amM[l] * 4 + amK[l]] = aU[l].x;
        Asb[1 * ASTR + amM[l] * 4 + amK[l]] = aU[l].y;
        Asb[2 * ASTR + amM[l] * 4 + amK[l]] = aU[l].z;
        Asb[3 * ASTR + amM[l] * 4 + amK[l]] = aU[l].w;
        *(uint4*)&Bsb[bcC[l] * ASTR + bnN[l] * 4] = bU[l];
    }
}

// ---------------------------------------------------------------------------
// Grounding layer 1 (fused A-gen, fp16 tensor cores):
// H1[r,c] = relu((f_i⊙v_j)@Wp + Apre[i,c] + Cpre[j,c] + b1[c]), r = i*160+j.
// ---------------------------------------------------------------------------
__global__ __launch_bounds__(256, 2) void ground_h1_tc(
    const float* __restrict__ f, const float* __restrict__ v,
    const float* __restrict__ b1)
{
    __shared__ uint32_t As[2][4 * ASTR];
    __shared__ uint32_t Bs[2][4 * ASTR];
    int tid = threadIdx.x;
    int lane = tid & 31, wid = tid >> 5;
    int wm = wid & 1, wn = wid >> 1;
    int wrow = wm * 64, wcol = wn * 32;
    int fr = lane >> 2, fc = lane & 3;
    int row0 = blockIdx.y * BM, col0 = blockIdx.x * BN;

    int amM[2], amK[2], bnN[2], bcC[2];
    const float *fp[2], *vp[2];
    const uint32_t* wp[2];
    #pragma unroll
    for (int l = 0; l < 2; l++) {
        int idx = tid + l * 256;
        amM[l] = idx >> 2; amK[l] = idx & 3;
        int gr = row0 + amM[l];
        int gi = gr / MJ, gj = gr - gi * MJ;
        fp[l] = f + (size_t)gi * DD + amK[l] * 8;
        vp[l] = v + (size_t)gj * DD + amK[l] * 8;
        bnN[l] = idx & 127; bcC[l] = idx >> 7;
        wp[l] = g_WpT + (size_t)bcC[l] * (HH * 4) + (size_t)(col0 + bnN[l]) * 4;
    }

    uint4 aU[2], bU[2];
    #pragma unroll
    for (int l = 0; l < 2; l++) {
        float4 fa = *(const float4*)fp[l];
        float4 fb = *(const float4*)(fp[l] + 4);
        float4 va = *(const float4*)vp[l];
        float4 vb = *(const float4*)(vp[l] + 4);
        aU[l] = make_uint4(pack_h2(fa.x * va.x, fa.y * va.y),
                           pack_h2(fa.z * va.z, fa.w * va.w),
                           pack_h2(fb.x * vb.x, fb.y * vb.y),
                           pack_h2(fb.z * vb.z, fb.w * vb.w));
        bU[l] = *(const uint4*)wp[l];
        fp[l] += BK; vp[l] += BK; wp[l] += HH * 16;
    }

    float acc[4][4][4] = {};
    int p = 0;
    for (int kt = 0; kt < DD; kt += BK) {
        sts_stage_u32(As[p], Bs[p], amM, amK, bnN, bcC, aU, bU);
        __syncthreads();
        if (kt + BK < DD) {
            #pragma unroll
            for (int l = 0; l < 2; l++) {
                float4 fa = *(const float4*)fp[l];
                float4 fb = *(const float4*)(fp[l] + 4);
                float4 va = *(const float4*)vp[l];
                float4 vb = *(const float4*)(vp[l] + 4);
                aU[l] = make_uint4(pack_h2(fa.x * va.x, fa.y * va.y),
                                   pack_h2(fa.z * va.z, fa.w * va.w),
                                   pack_h2(fb.x * vb.x, fb.y * vb.y),
                                   pack_h2(fb.z * vb.z, fb.w * vb.w));
                bU[l] = *(const uint4*)wp[l];
                fp[l] += BK; vp[l] += BK; wp[l] += HH * 16;
            }
        }
        mma_stage_f16(As[p], Bs[p], wrow, wcol, fr, fc, acc);
        p ^= 1;
    }

    #pragma unroll
    for (int mt = 0; mt < 4; mt++) {
        #pragma unroll
        for (int h = 0; h < 2; h++) {
            int r = row0 + wrow + mt * 16 + fr + h * 8;
            int gi = r / MJ, gj = r - gi * MJ;
            const float* ap = &g_Apre[(size_t)gi * HH];
            const float* cp = &g_Cpre[(size_t)gj * HH];
            uint32_t* hp = &g_H1[(size_t)r * (HH / 2)];
            #pragma unroll
            for (int nt = 0; nt < 4; nt++) {
                int c = col0 + wcol + nt * 8 + fc * 2;
                float x0 = acc[mt][nt][h * 2 + 0] + ap[c] + cp[c] + b1[c];
                float x1 = acc[mt][nt][h * 2 + 1] + ap[c + 1] + cp[c + 1] + b1[c + 1];
                hp[c >> 1] = pack_h2(fmaxf(x0, 0.f), fmaxf(x1, 0.f));
            }
        }
    }
}

// ---------------------------------------------------------------------------
// Text layer 1: g_Ht = relu(g_Xt @ tW1 + tb1). A packed-half2, B pre-transformed.
// ---------------------------------------------------------------------------
__global__ __launch_bounds__(256, 2) void text1_tc(const float* __restrict__ b1)
{
    __shared__ uint32_t As[2][4 * ASTR];
    __shared__ uint32_t Bs[2][4 * ASTR];
    int tid = threadIdx.x;
    int lane = tid & 31, wid = tid >> 5;
    int wm = wid & 1, wn = wid >> 1;
    int wrow = wm * 64, wcol = wn * 32;
    int fr = lane >> 2, fc = lane & 3;
    int row0 = blockIdx.y * BM, col0 = blockIdx.x * BN;

    int amM[2], amK[2], bnN[2], bcC[2], aOK[2];
    const uint32_t *xp[2], *wp[2];
    #pragma unroll
    for (int l = 0; l < 2; l++) {
        int idx = tid + l * 256;
        amM[l] = idx >> 2; amK[l] = idx & 3;
        int gr = row0 + amM[l];
        aOK[l] = (gr < MT);
        xp[l] = g_Xt + (size_t)(aOK[l] ? gr : 0) * (K3 / 2) + amK[l] * 4;
        bnN[l] = idx & 127; bcC[l] = idx >> 7;
        wp[l] = g_W1T + (size_t)bcC[l] * (HH * 4) + (size_t)(col0 + bnN[l]) * 4;
    }

    const uint4 zero4 = make_uint4(0, 0, 0, 0);
    uint4 aU[2], bU[2];
    #pragma unroll
    for (int l = 0; l < 2; l++) {
        aU[l] = aOK[l] ? *(const uint4*)xp[l] : zero4;
        bU[l] = *(const uint4*)wp[l];
        xp[l] += 16; wp[l] += HH * 16;
    }

    float acc[4][4][4] = {};
    int p = 0;
    for (int kt = 0; kt < K3; kt += BK) {
        sts_stage_u32(As[p], Bs[p], amM, amK, bnN, bcC, aU, bU);
        __syncthreads();
        if (kt + BK < K3) {
            #pragma unroll
            for (int l = 0; l < 2; l++) {
                aU[l] = aOK[l] ? *(const uint4*)xp[l] : zero4;
                bU[l] = *(const uint4*)wp[l];
                xp[l] += 16; wp[l] += HH * 16;
            }
        }
        mma_stage_f16(As[p], Bs[p], wrow, wcol, fr, fc, acc);
        p ^= 1;
    }

    #pragma unroll
    for (int mt = 0; mt < 4; mt++) {
        #pragma unroll
        for (int h = 0; h < 2; h++) {
            int r = row0 + wrow + mt * 16 + fr + h * 8;
            if (r >= MT) continue;
            uint32_t* hp = &g_Ht[(size_t)r * (HH / 2)];
            #pragma unroll
            for (int nt = 0; nt < 4; nt++) {
                int c = col0 + wcol + nt * 8 + fc * 2;
                float x0 = acc[mt][nt][h * 2 + 0] + b1[c];
                float x1 = acc[mt][nt][h * 2 + 1] + b1[c + 1];
                hp[c >> 1] = pack_h2(fmaxf(x0, 0.f), fmaxf(x1, 0.f));
            }
        }
    }
}

// ---------------------------------------------------------------------------
// Fused tail (fp16): out[r] = relu(H[r,:]@W2 + b2) @ W3 + b3 (optional mask).
// h_sel: 0 -> g_H1/g_W2gT, 1 -> g_Ht/g_W2tT.
// ---------------------------------------------------------------------------
__global__ __launch_bounds__(256, 2) void tail_tc(
    int h_sel, const float* __restrict__ b2, const float* __restrict__ W3,
    const float* __restrict__ b3v, const float* __restrict__ sm,
    const float* __restrict__ im, float* __restrict__ outp,
    int M, int masked)
{
    const uint32_t* Hm = (h_sel == 0) ? g_H1 : g_Ht;
    const uint32_t* W2T = (h_sel == 0) ? g_W2gT : g_W2tT;
    __shared__ uint32_t As[2][4 * ASTR];
    __shared__ uint32_t Bs[2][4 * ASTR];
    __shared__ float red[BM * 16];
    int tid = threadIdx.x;
    int lane = tid & 31, wid = tid >> 5;
    int wm = wid & 1, wn = wid >> 1;
    int wrow = wm * 64, wcol = wn * 32;
    int fr = lane >> 2, fc = lane & 3;
    int row0 = blockIdx.x * BM;
    float rsum[4][2] = {};

    int amM[2], amK[2], bnN[2], bcC[2], aOK[2];
    size_t aBase[2], bCol[2];
    #pragma unroll
    for (int l = 0; l < 2; l++) {
        int idx = tid + l * 256;
        amM[l] = idx >> 2; amK[l] = idx & 3;
        int gr = row0 + amM[l];
        aOK[l] = (gr < M);
        aBase[l] = (size_t)(aOK[l] ? gr : 0) * (HH / 2) + amK[l] * 4;
        bnN[l] = idx & 127; bcC[l] = idx >> 7;
        bCol[l] = (size_t)bcC[l] * (HH * 4);
    }

    const uint4 zero4 = make_uint4(0, 0, 0, 0);
    int p = 0;
    for (int nc = 0; nc < HH; nc += BN) {
        const uint32_t *hp2[2], *wp[2];
        uint4 aU[2], bU[2];
        #pragma unroll
        for (int l = 0; l < 2; l++) {
            hp2[l] = Hm + aBase[l];
            wp[l] = W2T + bCol[l] + (size_t)(nc + bnN[l]) * 4;
            aU[l] = aOK[l] ? *(const uint4*)hp2[l] : zero4;
            bU[l] = *(const uint4*)wp[l];
            hp2[l] += 16; wp[l] += HH * 16;
        }
        float acc[4][4][4] = {};
        for (int kt = 0; kt < HH; kt += BK) {
            sts_stage_u32(As[p], Bs[p], amM, amK, bnN, bcC, aU, bU);
            __syncthreads();
            if (kt + BK < HH) {
                #pragma unroll
                for (int l = 0; l < 2; l++) {
                    aU[l] = aOK[l] ? *(const uint4*)hp2[l] : zero4;
                    bU[l] = *(const uint4*)wp[l];
                    hp2[l] += 16; wp[l] += HH * 16;
                }
            }
            mma_stage_f16(As[p], Bs[p], wrow, wcol, fr, fc, acc);
            p ^= 1;
        }
        #pragma unroll
        for (int mt = 0; mt < 4; mt++) {
            #pragma unroll
            for (int nt = 0; nt < 4; nt++) {
                int c = nc + wcol + nt * 8 + fc * 2;
                float w30 = W3[c], w31 = W3[c + 1];
                float b20 = b2[c], b21 = b2[c + 1];
                rsum[mt][0] += fmaxf(acc[mt][nt][0] + b20, 0.f) * w30
                             + fmaxf(acc[mt][nt][1] + b21, 0.f) * w31;
                rsum[mt][1] += fmaxf(acc[mt][nt][2] + b20, 0.f) * w30
                             + fmaxf(acc[mt][nt][3] + b21, 0.f) * w31;
            }
        }
    }

    #pragma unroll
    for (int mt = 0; mt < 4; mt++)
        #pragma unroll
        for (int h = 0; h < 2; h++) {
            int row = wrow + mt * 16 + fr + h * 8;
            red[row * 16 + wn * 4 + fc] = rsum[mt][h];
        }
    __syncthreads();
    if (tid < BM) {
        int r = row0 + tid;
        if (r < M) {
            float s = 0.f;
            #pragma unroll
            for (int t = 0; t < 16; t++) s += red[tid * 16 + t];
            s += b3v[0];
            if (masked) {
                int gi = r / MJ, gj = r - gi * MJ;
                s *= sm[gi] * im[gj];
            }
            outp[r] = s;
        }
    }
}

// ---------------------------------------------------------------------------
// Small SGEMM (fp32, 64x64 tile) for the two tiny pre-GEMMs f@Wf, v@Ws.
// ---------------------------------------------------------------------------
__global__ __launch_bounds__(256) void sgemm_small(
    const float* __restrict__ A, const float* __restrict__ Bm,
    int c_sel, int M, int N, int K)
{
    float* C = (c_sel == 0) ? g_Apre : g_Cpre;
    __shared__ __align__(16) float As[16][66];
    __shared__ __align__(16) float Bs[16][64];
    int tid = threadIdx.x;
    int tx = tid & 15, ty = tid >> 4;
    int row0 = blockIdx.y * 64, col0 = blockIdx.x * 64;
    float acc[4][4] = {};
    for (int kt = 0; kt < K; kt += 16) {
        #pragma unroll
        for (int l = 0; l < 4; l++) {
            int idx = tid + l * 256;
            int m = idx >> 4, kk = idx & 15;
            int gr = row0 + m;
            As[kk][m] = (gr < M) ? A[(size_t)gr * K + kt + kk] : 0.f;
        }
        #pragma unroll
        for (int l = 0; l < 4; l++) {
            int idx = tid + l * 256;
            int kk = idx >> 6, c = idx & 63;
            Bs[kk][c] = Bm[(size_t)(kt + kk) * N + col0 + c];
        }
        __syncthreads();
        #pragma unroll
        for (int kk = 0; kk < 16; kk++) {
            float av[4];
            #pragma unroll
            for (int i = 0; i < 4; i++) av[i] = As[kk][ty * 4 + i];
            float4 b4 = *(const float4*)&Bs[kk][tx * 4];
            float bv[4] = {b4.x, b4.y, b4.z, b4.w};
            #pragma unroll
            for (int i = 0; i < 4; i++)
                #pragma unroll
                for (int j = 0; j < 4; j++)
                    acc[i][j] += av[i] * bv[j];
        }
        __syncthreads();
    }
    #pragma unroll
    for (int i = 0; i < 4; i++) {
        int r = row0 + ty * 4 + i;
        if (r >= M) continue;
        #pragma unroll
        for (int j = 0; j < 4; j++)
            C[(size_t)r * N + col0 + tx * 4 + j] = acc[i][j];
    }
}

// ---------------------------------------------------------------------------
// Build text concat input (packed half2):
// Xt[b*780+p] = [span[fi], span[si], span[fi]*span[si]]
// ---------------------------------------------------------------------------
__global__ void build_xt_kernel(const float* __restrict__ span)
{
    int r = blockIdx.x;
    int b = r / NPAIR, p = r - b * NPAIR;
    int n = 0, rem = p;
    while (rem >= (NS - 1 - n)) { rem -= (NS - 1 - n); n++; }
    int fi = n, si = n + 1 + rem;
    const float2* a2 = (const float2*)(span + ((size_t)b * NS + fi) * DD);
    const float2* c2 = (const float2*)(span + ((size_t)b * NS + si) * DD);
    uint32_t* x = g_Xt + (size_t)r * (K3 / 2);
    for (int d = threadIdx.x; d < DD / 2; d += blockDim.x) {
        float2 aa = a2[d], cc = c2[d];
        x[d] = pack_h2(aa.x, aa.y);
        x[DD / 2 + d] = pack_h2(cc.x, cc.y);
        x[DD + d] = pack_h2(aa.x * cc.x, aa.y * cc.y);
    }
}

// ---------------------------------------------------------------------------
// S[8][8] = chunk sums of 800 grounding scores; loss = bidirectional NCE.
// ---------------------------------------------------------------------------
__global__ void loss_kernel(const float* __restrict__ gsc, float* __restrict__ out0)
{
    __shared__ float S[64];
    __shared__ float red[256];
    int tid = threadIdx.x;
    int e = tid >> 2, q = tid & 3;
    float s = 0.f;
    const float* base = gsc + e * 800;
    for (int k = q; k < 800; k += 4) s += base[k];
    red[tid] = s;
    __syncthreads();
    if (q == 0) S[e] = red[tid] + red[tid + 1] + red[tid + 2] + red[tid + 3];
    __syncthreads();
    if (tid == 0) {
        float loss = 0.f;
        for (int a = 0; a < 8; a++) {
            float mx = -1e30f;
            for (int b = 0; b < 8; b++) mx = fmaxf(mx, S[a * 8 + b]);
            float se = 0.f;
            for (int b = 0; b < 8; b++) se += expf(S[a * 8 + b] - mx);
            float lse = mx + logf(se);
            for (int b = 0; b < 8; b++) loss -= (S[a * 8 + b] - lse);
        }
        for (int b = 0; b < 8; b++) {
            float mx = -1e30f;
            for (int a = 0; a < 8; a++) mx = fmaxf(mx, S[a * 8 + b]);
            float se = 0.f;
            for (int a = 0; a < 8; a++) se += expf(S[a * 8 + b] - mx);
            float lse = mx + logf(se);
            for (int a = 0; a < 8; a++) loss -= (S[a * 8 + b] - lse);
        }
        out0[0] = loss / 8.0f;
    }
}

extern "C" void kernel_launch(void* const* d_in, const int* in_sizes, int n_in,
                              void* d_out, int out_size)
{
    const float* span  = (const float*)d_in[0];
    const float* img   = (const float*)d_in[1];
    const float* smask = (const float*)d_in[2];
    const float* imask = (const float*)d_in[3];
    const float* tW1 = (const float*)d_in[4];
    const float* tb1 = (const float*)d_in[5];
    const float* tW2 = (const float*)d_in[6];
    const float* tb2 = (const float*)d_in[7];
    const float* tW3 = (const float*)d_in[8];
    const float* tb3 = (const float*)d_in[9];
    const float* gW1 = (const float*)d_in[10];
    const float* gb1 = (const float*)d_in[11];
    const float* gW2 = (const float*)d_in[12];
    const float* gb2 = (const float*)d_in[13];
    const float* gW3 = (const float*)d_in[14];
    const float* gb3 = (const float*)d_in[15];
    float* out = (float*)d_out;

    dim3 blk(256);

    // Fork a second stream for the independent text path (capture-legal
    // fork/join via events).
    cudaStream_t s2;
    cudaStreamCreateWithFlags(&s2, cudaStreamNonBlocking);
    cudaEvent_t evFork, evJoin;
    cudaEventCreateWithFlags(&evFork, cudaEventDisableTiming);
    cudaEventCreateWithFlags(&evJoin, cudaEventDisableTiming);

    cudaEventRecord(evFork, 0);
    cudaStreamWaitEvent(s2, evFork, 0);

    // ---- Text path on s2 ----
    wconv_kernel<<<(K3 * 512 + 255) / 256, blk, 0, s2>>>(tW1, 1, K3);
    wconv_kernel<<<(HH * 512 + 255) / 256, blk, 0, s2>>>(tW2, 3, HH);
    build_xt_kernel<<<dim3(MT), blk, 0, s2>>>(span);
    text1_tc<<<dim3(HH / BN, (MT + BM - 1) / BM), blk, 0, s2>>>(tb1);
    tail_tc<<<dim3((MT + BM - 1) / BM), blk, 0, s2>>>(1, tb2, tW3, tb3,
                                                      nullptr, nullptr,
                                                      out + 1 + MG, MT, 0);
    cudaEventRecord(evJoin, s2);

    // ---- Grounding path on the capture (default) stream ----
    wconv_kernel<<<(DD * 512 + 255) / 256, blk>>>(gW1 + (size_t)2 * DD * HH, 0, DD);
    wconv_kernel<<<(HH * 512 + 255) / 256, blk>>>(gW2, 2, HH);
    sgemm_small<<<dim3(16, 5), blk>>>(span, gW1, 0, MI, HH, DD);
    sgemm_small<<<dim3(16, 3), blk>>>(img, gW1 + (size_t)DD * HH, 1, MJ, HH, DD);
    ground_h1_tc<<<dim3(HH / BN, MG / BM), blk>>>(span, img, gb1);
    tail_tc<<<dim3(MG / BM), blk>>>(0, gb2, gW3, gb3, smask, imask, out + 1, MG, 1);

    // Join text path before the final reduction.
    cudaStreamWaitEvent(0, evJoin, 0);
    loss_kernel<<<1, 256>>>(out + 1, out);
}